// round 8
// baseline (speedup 1.0000x reference)
#include <cuda_runtime.h>
#include <cuda_fp16.h>
#include <cstdint>

// Problem constants
#define NHEAD   8
#define DK      64
#define LEN     100
#define BS      32
#define DMODEL  512
#define TEMP    20.0f
#define LN8192  9.0109133f

// Pre-split normalized projections (fp16 hi/lo): [b][h][128 rows][64] packed as
// 32 u32 words/row. Rows 100..127 never written -> stay zero = free padding.
__device__ __align__(16) uint32_t g_Qhi[BS * NHEAD * 128 * 32];
__device__ __align__(16) uint32_t g_Qlo[BS * NHEAD * 128 * 32];
__device__ __align__(16) uint32_t g_Khi[BS * NHEAD * 128 * 32];
__device__ __align__(16) uint32_t g_Klo[BS * NHEAD * 128 * 32];
// V^T images per (kb,h): 64 d-rows x 60 words (fp16 pairs, m pairs 0..111,
// m>=100 zero, words 56..59 pad). Exactly the smem image attn wants.
__device__ __align__(16) uint32_t g_Vhi[BS * NHEAD * 64 * 60];
__device__ __align__(16) uint32_t g_Vlo[BS * NHEAD * 64 * 60];

// ---------------------------------------------------------------------------
__device__ __forceinline__ void mma_f16(float c[4],
    uint32_t a0, uint32_t a1, uint32_t a2, uint32_t a3,
    uint32_t b0, uint32_t b1)
{
    asm volatile(
        "mma.sync.aligned.m16n8k16.row.col.f32.f16.f16.f32 "
        "{%0,%1,%2,%3}, {%4,%5,%6,%7}, {%8,%9}, {%0,%1,%2,%3};"
        : "+f"(c[0]), "+f"(c[1]), "+f"(c[2]), "+f"(c[3])
        : "r"(a0), "r"(a1), "r"(a2), "r"(a3), "r"(b0), "r"(b1));
}

__device__ __forceinline__ void split2h(float x0, float x1,
                                        uint32_t& hi, uint32_t& lo)
{
    __half2 h = __floats2half2_rn(x0, x1);
    float2 hf = __half22float2(h);
    __half2 l = __floats2half2_rn(x0 - hf.x, x1 - hf.y);
    hi = *(uint32_t*)&h;
    lo = *(uint32_t*)&l;
}

// ---------------------------------------------------------------------------
// Kernel 1: projection via fp16 3-term mma + fused L2-norm (unchanged, 59us)
// ---------------------------------------------------------------------------
#define PJ_AHI 0
#define PJ_ALO 16128
#define PJ_BHI 32256
#define PJ_BLO 41472
#define PJ_SMEM 50688

__global__ __launch_bounds__(256) void proj_kernel(
    const float* __restrict__ q, const float* __restrict__ k,
    const float* __restrict__ w_qs, const float* __restrict__ w_ks)
{
    extern __shared__ char sm[];
    uint32_t* AHI = (uint32_t*)(sm + PJ_AHI);
    uint32_t* ALO = (uint32_t*)(sm + PJ_ALO);
    uint32_t* BHI = (uint32_t*)(sm + PJ_BHI);
    uint32_t* BLO = (uint32_t*)(sm + PJ_BLO);
    float* S = (float*)sm;

    const int cb = blockIdx.x, b = blockIdx.y, sel = blockIdx.z;
    const float* x = sel ? k : q;
    const float* w = sel ? w_ks : w_qs;
    uint32_t* GH = sel ? g_Khi : g_Qhi;
    uint32_t* GL = sel ? g_Klo : g_Qlo;

    const int tid = threadIdx.x;
    const int warp = tid >> 5, lane = tid & 31;
    const int g = lane >> 2, t = lane & 3;

    float4 pa[7], pb[4];

    #pragma unroll
    for (int u = 0; u < 7; u++) {
        const int i = tid + 256 * u, r = i >> 4, c4 = i & 15;
        pa[u] = (r < LEN)
            ? *(const float4*)(x + (size_t)(b * 100 + r) * DMODEL + c4 * 4)
            : make_float4(0.f, 0.f, 0.f, 0.f);
    }
    #pragma unroll
    for (int u = 0; u < 4; u++) {
        const int i = tid + 256 * u, r = i >> 4, c4 = i & 15;
        pb[u] = *(const float4*)(w + (size_t)(cb * 64 + r) * DMODEL + c4 * 4);
    }

    float acc[7][4] = {};

    for (int c = 0; c < 8; c++) {
        __syncthreads();
        #pragma unroll
        for (int u = 0; u < 7; u++) {
            const int i = tid + 256 * u, r = i >> 4, c4 = i & 15;
            uint32_t h0, l0, h1, l1;
            split2h(pa[u].x, pa[u].y, h0, l0);
            split2h(pa[u].z, pa[u].w, h1, l1);
            AHI[r * 36 + c4 * 2] = h0; AHI[r * 36 + c4 * 2 + 1] = h1;
            ALO[r * 36 + c4 * 2] = l0; ALO[r * 36 + c4 * 2 + 1] = l1;
        }
        #pragma unroll
        for (int u = 0; u < 4; u++) {
            const int i = tid + 256 * u, r = i >> 4, c4 = i & 15;
            uint32_t h0, l0, h1, l1;
            split2h(pb[u].x, pb[u].y, h0, l0);
            split2h(pb[u].z, pb[u].w, h1, l1);
            BHI[r * 36 + c4 * 2] = h0; BHI[r * 36 + c4 * 2 + 1] = h1;
            BLO[r * 36 + c4 * 2] = l0; BLO[r * 36 + c4 * 2 + 1] = l1;
        }
        __syncthreads();
        if (c < 7) {
            const int k0 = (c + 1) * 64;
            #pragma unroll
            for (int u = 0; u < 7; u++) {
                const int i = tid + 256 * u, r = i >> 4, c4 = i & 15;
                pa[u] = (r < LEN)
                    ? *(const float4*)(x + (size_t)(b * 100 + r) * DMODEL + k0 + c4 * 4)
                    : make_float4(0.f, 0.f, 0.f, 0.f);
            }
            #pragma unroll
            for (int u = 0; u < 4; u++) {
                const int i = tid + 256 * u, r = i >> 4, c4 = i & 15;
                pb[u] = *(const float4*)(w + (size_t)(cb * 64 + r) * DMODEL + k0 + c4 * 4);
            }
        }
        #pragma unroll
        for (int ks = 0; ks < 4; ks++) {
            const int nb = (warp * 8 + g) * 36 + ks * 8 + t;
            const uint32_t bh0 = BHI[nb], bh1 = BHI[nb + 4];
            const uint32_t bl0 = BLO[nb], bl1 = BLO[nb + 4];
            #pragma unroll
            for (int i = 0; i < 7; i++) {
                const int rb = (i * 16 + g) * 36 + ks * 8 + t;
                const uint32_t ah0 = AHI[rb], ah1 = AHI[rb + 288];
                const uint32_t ah2 = AHI[rb + 4], ah3 = AHI[rb + 292];
                const uint32_t al0 = ALO[rb], al1 = ALO[rb + 288];
                const uint32_t al2 = ALO[rb + 4], al3 = ALO[rb + 292];
                mma_f16(acc[i], ah0, ah1, ah2, ah3, bh0, bh1);
                mma_f16(acc[i], ah0, ah1, ah2, ah3, bl0, bl1);
                mma_f16(acc[i], al0, al1, al2, al3, bh0, bh1);
            }
        }
    }
    __syncthreads();

    #pragma unroll
    for (int i = 0; i < 7; i++) {
        const int cc = warp * 8 + 2 * t;
        *(float2*)(S + (i * 16 + g) * 68 + cc)     = make_float2(acc[i][0], acc[i][1]);
        *(float2*)(S + (i * 16 + g + 8) * 68 + cc) = make_float2(acc[i][2], acc[i][3]);
    }
    __syncthreads();

    if (tid < LEN) {
        const float* Sr = S + tid * 68;
        float ss = 0.0f;
        #pragma unroll
        for (int u = 0; u < 16; u++) {
            float4 xv = *(const float4*)(Sr + u * 4);
            ss += xv.x * xv.x + xv.y * xv.y + xv.z * xv.z + xv.w * xv.w;
        }
        const float inv = 1.0f / fmaxf(sqrtf(ss), 1e-12f);
        const int n = tid * 8 + cb;
        const int hh = n / 100, ll = n % 100;
        const uint32_t base = ((uint32_t)(b * 8 + hh) * 128 + ll) * 32;
        #pragma unroll
        for (int u = 0; u < 16; u++) {
            float4 xv = *(const float4*)(Sr + u * 4);
            uint32_t h0, l0, h1, l1;
            split2h(xv.x * inv, xv.y * inv, h0, l0);
            split2h(xv.z * inv, xv.w * inv, h1, l1);
            GH[base + u * 2] = h0; GH[base + u * 2 + 1] = h1;
            GL[base + u * 2] = l0; GL[base + u * 2 + 1] = l1;
        }
    }
}

// ---------------------------------------------------------------------------
// Kernel 2: build V^T fp16 hi/lo smem images in gmem (unchanged)
// ---------------------------------------------------------------------------
__global__ __launch_bounds__(256) void vimg_kernel(const float* __restrict__ v)
{
    __shared__ uint32_t sh[64 * 60], sl[64 * 60];
    const int bh = blockIdx.x;
    const int kb = bh >> 3, h = bh & 7;
    const float* vp = v + (size_t)kb * 51200 + h * 6400;
    const int tid = threadIdx.x;

    for (int e = tid; e < 64 * 60; e += 256) { sh[e] = 0u; sl[e] = 0u; }
    __syncthreads();
    for (int e = tid; e < 64 * 56; e += 256) {
        const int w = e >> 6, d = e & 63;
        const int m0 = 2 * w, m1 = 2 * w + 1;
        float x0 = (m0 < LEN) ? vp[m0 * 64 + d] : 0.0f;
        float x1 = (m1 < LEN) ? vp[m1 * 64 + d] : 0.0f;
        uint32_t hw, lw;
        split2h(x0, x1, hw, lw);
        sh[d * 60 + w] = hw;
        sl[d * 60 + w] = lw;
    }
    __syncthreads();
    uint4* GH = (uint4*)(g_Vhi + (size_t)bh * 3840);
    uint4* GL = (uint4*)(g_Vlo + (size_t)bh * 3840);
    const uint4* SH = (const uint4*)sh;
    const uint4* SL = (const uint4*)sl;
    for (int e = tid; e < 960; e += 256) { GH[e] = SH[e]; GL[e] = SL[e]; }
}

// ---------------------------------------------------------------------------
// Kernel 3: attention per (qb,kb,h), 8 warps, M=112.
//   S[112x104]: warps 0-6 own m16 strip i=w, j=0..11 (cols 0..95, no mask);
//               warp 7 owns j=12 (cols 96..103, masked) for all i.
//   P = exp(20*relu(S) - ln8192) fp16, overlays Q smem. Rowsums: 2 slots/row.
//   O[112x64] = P V (2-term): warp = n8 strip, 7 m-tiles, B-frag reuse.
// P cols 104-111 are never written; V rows 104-111 are zero, so the stale
// (finite) fp16 garbage there multiplies zero in the O mma.
// ---------------------------------------------------------------------------
#define OFF_RS   0                       // 112 rows x 2 floats (pad to 1024)
#define OFF_QHI  1024                    // 112 x 36 words = 16128B each
#define OFF_QLO  17152
#define OFF_KHI  33280
#define OFF_KLO  49408
#define OFF_VHI  65536                   // 64 x 60 words = 15360B each
#define OFF_VLO  80896
#define ATTN_SMEM 96256                  // -> 2 CTAs/SM
#define OFF_P    1024                    // overlays Q: 112 x 60 words = 26880B

__global__ __launch_bounds__(256, 2) void attn_kernel(float* __restrict__ out)
{
    extern __shared__ char sm[];
    float* RS = (float*)(sm + OFF_RS);
    uint32_t* QHI = (uint32_t*)(sm + OFF_QHI);
    uint32_t* QLO = (uint32_t*)(sm + OFF_QLO);
    uint32_t* KHI = (uint32_t*)(sm + OFF_KHI);
    uint32_t* KLO = (uint32_t*)(sm + OFF_KLO);
    uint32_t* VHI = (uint32_t*)(sm + OFF_VHI);
    uint32_t* VLO = (uint32_t*)(sm + OFF_VLO);
    uint32_t* P   = (uint32_t*)(sm + OFF_P);

    const int bx = blockIdx.x;
    const int h  = bx & 7;
    const int qb = (bx >> 3) & 31;
    const int kb = bx >> 8;
    const int tid = threadIdx.x;
    const int warp = tid >> 5, lane = tid & 31;
    const int g = lane >> 2, t = lane & 3;

    // ---- staging: pure uint4 copies (first 112 rows of Q/K images)
    {
        const uint4* sqh = (const uint4*)(g_Qhi + (size_t)(qb * 8 + h) * 4096);
        const uint4* sql = (const uint4*)(g_Qlo + (size_t)(qb * 8 + h) * 4096);
        const uint4* skh = (const uint4*)(g_Khi + (size_t)(kb * 8 + h) * 4096);
        const uint4* skl = (const uint4*)(g_Klo + (size_t)(kb * 8 + h) * 4096);
        uint4* dqh = (uint4*)QHI; uint4* dql = (uint4*)QLO;
        uint4* dkh = (uint4*)KHI; uint4* dkl = (uint4*)KLO;
        for (int i = tid; i < 896; i += 256) {        // 112 rows x 8 uint4
            const int r = i >> 3, c = i & 7;
            const int s = r * 8 + c, d = r * 9 + c;   // gmem 32w, smem 36w rows
            dqh[d] = sqh[s]; dql[d] = sql[s];
            dkh[d] = skh[s]; dkl[d] = skl[s];
        }
        const uint4* svh = (const uint4*)(g_Vhi + (size_t)(kb * 8 + h) * 3840);
        const uint4* svl = (const uint4*)(g_Vlo + (size_t)(kb * 8 + h) * 3840);
        uint4* dvh = (uint4*)VHI; uint4* dvl = (uint4*)VLO;
        for (int i = tid; i < 960; i += 256) { dvh[i] = svh[i]; dvl[i] = svl[i]; }
    }
    __syncthreads();

    // ---- S phase (shared acc: warps 0-6 use all 12, warp 7 uses 7)
    float acc[12][4] = {};
    if (warp < 7) {
        // strip i = warp: A-frag loaded once per ks, reused over 12 j-tiles
        #pragma unroll
        for (int ks = 0; ks < 4; ks++) {
            const int rb = (warp * 16 + g) * 36 + ks * 8 + t;
            const uint32_t ah0 = QHI[rb],       ah1 = QHI[rb + 288];
            const uint32_t ah2 = QHI[rb + 4],   ah3 = QHI[rb + 292];
            const uint32_t al0 = QLO[rb],       al1 = QLO[rb + 288];
            const uint32_t al2 = QLO[rb + 4],   al3 = QLO[rb + 292];
            #pragma unroll
            for (int j = 0; j < 12; j++) {
                const int nb = (j * 8 + g) * 36 + ks * 8 + t;
                const uint32_t bh0 = KHI[nb], bh1 = KHI[nb + 4];
                const uint32_t bl0 = KLO[nb], bl1 = KLO[nb + 4];
                mma_f16(acc[j], ah0, ah1, ah2, ah3, bh0, bh1);
                mma_f16(acc[j], ah0, ah1, ah2, ah3, bl0, bl1);
                mma_f16(acc[j], al0, al1, al2, al3, bh0, bh1);
            }
        }
    } else {
        // strip j = 12 (cols 96..103): B-frag loaded once per ks, 7 i-tiles
        #pragma unroll
        for (int ks = 0; ks < 4; ks++) {
            const int nb = (96 + g) * 36 + ks * 8 + t;
            const uint32_t bh0 = KHI[nb], bh1 = KHI[nb + 4];
            const uint32_t bl0 = KLO[nb], bl1 = KLO[nb + 4];
            #pragma unroll
            for (int i = 0; i < 7; i++) {
                const int rb = (i * 16 + g) * 36 + ks * 8 + t;
                const uint32_t ah0 = QHI[rb],       ah1 = QHI[rb + 288];
                const uint32_t ah2 = QHI[rb + 4],   ah3 = QHI[rb + 292];
                const uint32_t al0 = QLO[rb],       al1 = QLO[rb + 288];
                const uint32_t al2 = QLO[rb + 4],   al3 = QLO[rb + 292];
                mma_f16(acc[i], ah0, ah1, ah2, ah3, bh0, bh1);
                mma_f16(acc[i], ah0, ah1, ah2, ah3, bl0, bl1);
                mma_f16(acc[i], al0, al1, al2, al3, bh0, bh1);
            }
        }
    }
    __syncthreads();   // all Q/K reads done before P overlays Q smem

    // ---- epilogue: e = exp(20*relu(s) - ln8192), pack fp16, rowsums
    if (warp < 7) {
        // rows 16*warp+g, +8; cols 0..95 -> no column mask needed
        float rs0 = 0.0f, rs8 = 0.0f;
        #pragma unroll
        for (int j = 0; j < 12; j++) {
            float e0 = __expf(fmaf(TEMP, fmaxf(acc[j][0], 0.f), -LN8192));
            float e1 = __expf(fmaf(TEMP, fmaxf(acc[j][1], 0.f), -LN8192));
            float e2 = __expf(fmaf(TEMP, fmaxf(acc[j][2], 0.f), -LN8192));
            float e3 = __expf(fmaf(TEMP, fmaxf(acc[j][3], 0.f), -LN8192));
            __half2 h01 = __floats2half2_rn(e0, e1);
            __half2 h23 = __floats2half2_rn(e2, e3);
            float2 f01 = __half22float2(h01);
            float2 f23 = __half22float2(h23);
            rs0 += f01.x + f01.y;
            rs8 += f23.x + f23.y;
            const int w0 = (warp * 16 + g) * 60 + j * 4 + t;
            P[w0]       = *(uint32_t*)&h01;
            P[w0 + 480] = *(uint32_t*)&h23;
        }
        rs0 += __shfl_xor_sync(0xffffffffu, rs0, 1);
        rs0 += __shfl_xor_sync(0xffffffffu, rs0, 2);
        rs8 += __shfl_xor_sync(0xffffffffu, rs8, 1);
        rs8 += __shfl_xor_sync(0xffffffffu, rs8, 2);
        if (t == 0) {
            RS[(warp * 16 + g) * 2]     = rs0;
            RS[(warp * 16 + g + 8) * 2] = rs8;
        }
    } else {
        // cols 96+2t (mask >= 100: lanes t>=2 are fully dead)
        const int col = 96 + 2 * t;
        #pragma unroll
        for (int i = 0; i < 7; i++) {
            float e0 = 0.f, e1 = 0.f, e2 = 0.f, e3 = 0.f;
            if (col < LEN) {
                e0 = __expf(fmaf(TEMP, fmaxf(acc[i][0], 0.f), -LN8192));
                e1 = __expf(fmaf(TEMP, fmaxf(acc[i][1], 0.f), -LN8192));
                e2 = __expf(fmaf(TEMP, fmaxf(acc[i][2], 0.f), -LN8192));
                e3 = __expf(fmaf(TEMP, fmaxf(acc[i][3], 0.f), -LN8192));
            }
            __half2 h01 = __floats2half2_rn(e0, e1);
            __half2 h23 = __floats2half2_rn(e2, e3);
            float2 f01 = __half22float2(h01);
            float2 f23 = __half22float2(h23);
            float rs0 = f01.x + f01.y;
            float rs8 = f23.x + f23.y;
            rs0 += __shfl_xor_sync(0xffffffffu, rs0, 1);
            rs0 += __shfl_xor_sync(0xffffffffu, rs0, 2);
            rs8 += __shfl_xor_sync(0xffffffffu, rs8, 1);
            rs8 += __shfl_xor_sync(0xffffffffu, rs8, 2);
            if (t == 0) {
                RS[(i * 16 + g) * 2 + 1]     = rs0;
                RS[(i * 16 + g + 8) * 2 + 1] = rs8;
            }
            const int w0 = (i * 16 + g) * 60 + 48 + t;
            P[w0]       = *(uint32_t*)&h01;
            P[w0 + 480] = *(uint32_t*)&h23;
        }
    }
    __syncthreads();

    // ---- O phase: warp = n8 strip, 7 m-tiles, K = 112 (7 k-steps, 2-term)
    float o[7][4] = {};
    #pragma unroll
    for (int ks = 0; ks < 7; ks++) {
        const int nb = (warp * 8 + g) * 60 + ks * 8 + t;
        const uint32_t bh0 = VHI[nb], bh1 = VHI[nb + 4];
        const uint32_t bl0 = VLO[nb], bl1 = VLO[nb + 4];
        #pragma unroll
        for (int i = 0; i < 7; i++) {
            const int rb = (i * 16 + g) * 60 + ks * 8 + t;
            const uint32_t a0 = P[rb],     a1 = P[rb + 480];
            const uint32_t a2 = P[rb + 4], a3 = P[rb + 484];
            mma_f16(o[i], a0, a1, a2, a3, bh0, bh1);
            mma_f16(o[i], a0, a1, a2, a3, bl0, bl1);
        }
    }

    // ---- output: divide by rowsum, write [kb][qb][l][h*64 + warp*8 + 2t]
    const size_t ob = (size_t)(kb * 32 + qb) * LEN * DMODEL + h * 64
                      + warp * 8 + 2 * t;
    #pragma unroll
    for (int i = 0; i < 7; i++) {
        const int r = i * 16 + g;
        if (r < LEN) {
            const float inv = 1.0f / (RS[r * 2] + RS[r * 2 + 1]);
            *(float2*)(out + ob + (size_t)r * DMODEL) =
                make_float2(o[i][0] * inv, o[i][1] * inv);
        }
        if (r + 8 < LEN) {
            const float inv = 1.0f / (RS[(r + 8) * 2] + RS[(r + 8) * 2 + 1]);
            *(float2*)(out + ob + (size_t)(r + 8) * DMODEL) =
                make_float2(o[i][2] * inv, o[i][3] * inv);
        }
    }
}

// ---------------------------------------------------------------------------
extern "C" void kernel_launch(void* const* d_in, const int* in_sizes, int n_in,
                              void* d_out, int out_size)
{
    const float* q    = (const float*)d_in[0];
    const float* k    = (const float*)d_in[1];
    const float* v    = (const float*)d_in[2];
    const float* w_qs = (const float*)d_in[3];
    const float* w_ks = (const float*)d_in[4];
    float* out = (float*)d_out;

    cudaFuncSetAttribute(proj_kernel,
                         cudaFuncAttributeMaxDynamicSharedMemorySize, PJ_SMEM);
    cudaFuncSetAttribute(attn_kernel,
                         cudaFuncAttributeMaxDynamicSharedMemorySize, ATTN_SMEM);

    proj_kernel<<<dim3(8, 32, 2), 256, PJ_SMEM>>>(q, k, w_qs, w_ks);
    vimg_kernel<<<256, 256>>>(v);
    attn_kernel<<<8192, 256, ATTN_SMEM>>>(out);
}

// round 9
// speedup vs baseline: 1.0772x; 1.0772x over previous
#include <cuda_runtime.h>
#include <cuda_fp16.h>
#include <cstdint>

// Problem constants
#define NHEAD   8
#define DK      64
#define LEN     100
#define BS      32
#define DMODEL  512
#define TEMP    20.0f
#define LN8192  9.0109133f

// Pre-split normalized projections (fp16 hi/lo): [b][h][128 rows][64] packed as
// 32 u32 words/row. Rows 100..127 never written -> stay zero = free padding.
__device__ __align__(16) uint32_t g_Qhi[BS * NHEAD * 128 * 32];
__device__ __align__(16) uint32_t g_Qlo[BS * NHEAD * 128 * 32];
__device__ __align__(16) uint32_t g_Khi[BS * NHEAD * 128 * 32];
__device__ __align__(16) uint32_t g_Klo[BS * NHEAD * 128 * 32];
// V^T image per (kb,h): 64 d-rows x 60 words (fp16 pairs, m pairs 0..111,
// m>=100 zero, words 56..59 pad). Single fp16 term (O-phase error budget).
__device__ __align__(16) uint32_t g_Vhi[BS * NHEAD * 64 * 60];

// ---------------------------------------------------------------------------
__device__ __forceinline__ void mma_f16(float c[4],
    uint32_t a0, uint32_t a1, uint32_t a2, uint32_t a3,
    uint32_t b0, uint32_t b1)
{
    asm volatile(
        "mma.sync.aligned.m16n8k16.row.col.f32.f16.f16.f32 "
        "{%0,%1,%2,%3}, {%4,%5,%6,%7}, {%8,%9}, {%0,%1,%2,%3};"
        : "+f"(c[0]), "+f"(c[1]), "+f"(c[2]), "+f"(c[3])
        : "r"(a0), "r"(a1), "r"(a2), "r"(a3), "r"(b0), "r"(b1));
}

__device__ __forceinline__ void split2h(float x0, float x1,
                                        uint32_t& hi, uint32_t& lo)
{
    __half2 h = __floats2half2_rn(x0, x1);
    float2 hf = __half22float2(h);
    __half2 l = __floats2half2_rn(x0 - hf.x, x1 - hf.y);
    hi = *(uint32_t*)&h;
    lo = *(uint32_t*)&l;
}

// ---------------------------------------------------------------------------
// Kernel 1: projection via fp16 3-term mma + fused L2-norm (unchanged, 59us)
// ---------------------------------------------------------------------------
#define PJ_AHI 0
#define PJ_ALO 16128
#define PJ_BHI 32256
#define PJ_BLO 41472
#define PJ_SMEM 50688

__global__ __launch_bounds__(256) void proj_kernel(
    const float* __restrict__ q, const float* __restrict__ k,
    const float* __restrict__ w_qs, const float* __restrict__ w_ks)
{
    extern __shared__ char sm[];
    uint32_t* AHI = (uint32_t*)(sm + PJ_AHI);
    uint32_t* ALO = (uint32_t*)(sm + PJ_ALO);
    uint32_t* BHI = (uint32_t*)(sm + PJ_BHI);
    uint32_t* BLO = (uint32_t*)(sm + PJ_BLO);
    float* S = (float*)sm;

    const int cb = blockIdx.x, b = blockIdx.y, sel = blockIdx.z;
    const float* x = sel ? k : q;
    const float* w = sel ? w_ks : w_qs;
    uint32_t* GH = sel ? g_Khi : g_Qhi;
    uint32_t* GL = sel ? g_Klo : g_Qlo;

    const int tid = threadIdx.x;
    const int warp = tid >> 5, lane = tid & 31;
    const int g = lane >> 2, t = lane & 3;

    float4 pa[7], pb[4];

    #pragma unroll
    for (int u = 0; u < 7; u++) {
        const int i = tid + 256 * u, r = i >> 4, c4 = i & 15;
        pa[u] = (r < LEN)
            ? *(const float4*)(x + (size_t)(b * 100 + r) * DMODEL + c4 * 4)
            : make_float4(0.f, 0.f, 0.f, 0.f);
    }
    #pragma unroll
    for (int u = 0; u < 4; u++) {
        const int i = tid + 256 * u, r = i >> 4, c4 = i & 15;
        pb[u] = *(const float4*)(w + (size_t)(cb * 64 + r) * DMODEL + c4 * 4);
    }

    float acc[7][4] = {};

    for (int c = 0; c < 8; c++) {
        __syncthreads();
        #pragma unroll
        for (int u = 0; u < 7; u++) {
            const int i = tid + 256 * u, r = i >> 4, c4 = i & 15;
            uint32_t h0, l0, h1, l1;
            split2h(pa[u].x, pa[u].y, h0, l0);
            split2h(pa[u].z, pa[u].w, h1, l1);
            AHI[r * 36 + c4 * 2] = h0; AHI[r * 36 + c4 * 2 + 1] = h1;
            ALO[r * 36 + c4 * 2] = l0; ALO[r * 36 + c4 * 2 + 1] = l1;
        }
        #pragma unroll
        for (int u = 0; u < 4; u++) {
            const int i = tid + 256 * u, r = i >> 4, c4 = i & 15;
            uint32_t h0, l0, h1, l1;
            split2h(pb[u].x, pb[u].y, h0, l0);
            split2h(pb[u].z, pb[u].w, h1, l1);
            BHI[r * 36 + c4 * 2] = h0; BHI[r * 36 + c4 * 2 + 1] = h1;
            BLO[r * 36 + c4 * 2] = l0; BLO[r * 36 + c4 * 2 + 1] = l1;
        }
        __syncthreads();
        if (c < 7) {
            const int k0 = (c + 1) * 64;
            #pragma unroll
            for (int u = 0; u < 7; u++) {
                const int i = tid + 256 * u, r = i >> 4, c4 = i & 15;
                pa[u] = (r < LEN)
                    ? *(const float4*)(x + (size_t)(b * 100 + r) * DMODEL + k0 + c4 * 4)
                    : make_float4(0.f, 0.f, 0.f, 0.f);
            }
            #pragma unroll
            for (int u = 0; u < 4; u++) {
                const int i = tid + 256 * u, r = i >> 4, c4 = i & 15;
                pb[u] = *(const float4*)(w + (size_t)(cb * 64 + r) * DMODEL + k0 + c4 * 4);
            }
        }
        #pragma unroll
        for (int ks = 0; ks < 4; ks++) {
            const int nb = (warp * 8 + g) * 36 + ks * 8 + t;
            const uint32_t bh0 = BHI[nb], bh1 = BHI[nb + 4];
            const uint32_t bl0 = BLO[nb], bl1 = BLO[nb + 4];
            #pragma unroll
            for (int i = 0; i < 7; i++) {
                const int rb = (i * 16 + g) * 36 + ks * 8 + t;
                const uint32_t ah0 = AHI[rb], ah1 = AHI[rb + 288];
                const uint32_t ah2 = AHI[rb + 4], ah3 = AHI[rb + 292];
                const uint32_t al0 = ALO[rb], al1 = ALO[rb + 288];
                const uint32_t al2 = ALO[rb + 4], al3 = ALO[rb + 292];
                mma_f16(acc[i], ah0, ah1, ah2, ah3, bh0, bh1);
                mma_f16(acc[i], ah0, ah1, ah2, ah3, bl0, bl1);
                mma_f16(acc[i], al0, al1, al2, al3, bh0, bh1);
            }
        }
    }
    __syncthreads();

    #pragma unroll
    for (int i = 0; i < 7; i++) {
        const int cc = warp * 8 + 2 * t;
        *(float2*)(S + (i * 16 + g) * 68 + cc)     = make_float2(acc[i][0], acc[i][1]);
        *(float2*)(S + (i * 16 + g + 8) * 68 + cc) = make_float2(acc[i][2], acc[i][3]);
    }
    __syncthreads();

    if (tid < LEN) {
        const float* Sr = S + tid * 68;
        float ss = 0.0f;
        #pragma unroll
        for (int u = 0; u < 16; u++) {
            float4 xv = *(const float4*)(Sr + u * 4);
            ss += xv.x * xv.x + xv.y * xv.y + xv.z * xv.z + xv.w * xv.w;
        }
        const float inv = 1.0f / fmaxf(sqrtf(ss), 1e-12f);
        const int n = tid * 8 + cb;
        const int hh = n / 100, ll = n % 100;
        const uint32_t base = ((uint32_t)(b * 8 + hh) * 128 + ll) * 32;
        #pragma unroll
        for (int u = 0; u < 16; u++) {
            float4 xv = *(const float4*)(Sr + u * 4);
            uint32_t h0, l0, h1, l1;
            split2h(xv.x * inv, xv.y * inv, h0, l0);
            split2h(xv.z * inv, xv.w * inv, h1, l1);
            GH[base + u * 2] = h0; GH[base + u * 2 + 1] = h1;
            GL[base + u * 2] = l0; GL[base + u * 2 + 1] = l1;
        }
    }
}

// ---------------------------------------------------------------------------
// Kernel 2: build V^T single-fp16 smem image in gmem. One block per (kb,h).
// ---------------------------------------------------------------------------
__global__ __launch_bounds__(256) void vimg_kernel(const float* __restrict__ v)
{
    __shared__ uint32_t sh[64 * 60];
    const int bh = blockIdx.x;
    const int kb = bh >> 3, h = bh & 7;
    const float* vp = v + (size_t)kb * 51200 + h * 6400;
    const int tid = threadIdx.x;

    for (int e = tid; e < 64 * 60; e += 256) sh[e] = 0u;
    __syncthreads();
    for (int e = tid; e < 64 * 56; e += 256) {
        const int w = e >> 6, d = e & 63;
        const int m0 = 2 * w, m1 = 2 * w + 1;
        float x0 = (m0 < LEN) ? vp[m0 * 64 + d] : 0.0f;
        float x1 = (m1 < LEN) ? vp[m1 * 64 + d] : 0.0f;
        __half2 hv = __floats2half2_rn(x0, x1);
        sh[d * 60 + w] = *(uint32_t*)&hv;
    }
    __syncthreads();
    uint4* GH = (uint4*)(g_Vhi + (size_t)bh * 3840);
    const uint4* SH = (const uint4*)sh;
    for (int e = tid; e < 960; e += 256) GH[e] = SH[e];
}

// ---------------------------------------------------------------------------
// Kernel 3: attention per (qb,kb,h), 8 warps — round-7 structure, fp16.
//   S[128x112] = Q K^T   (3-term fp16; warps 4M x 2N; wn=1 skips dead strip)
//   P = exp(20*relu(S) - ln8192) masked, single fp16, overlays Q smem
//   O[128x64]  = P V     (1-term: V single fp16)
// Rowsums from the ROUNDED fp16 P (common-mode rounding cancels in divide).
// ---------------------------------------------------------------------------
#define OFF_RS   0                       // 128 rows x 2 floats = 1024B
#define OFF_QHI  1024                    // 128 x 36 words = 18432B
#define OFF_QLO  19456
#define OFF_KHI  37888                   // 112 x 36 words = 16128B
#define OFF_KLO  54016
#define OFF_VHI  70144                   // 64 x 60 words = 15360B
#define ATTN_SMEM 85504                  // -> 2 CTAs/SM
#define OFF_P    1024                    // overlays QHI/QLO: 128 x 60 w = 30720B

__global__ __launch_bounds__(256, 2) void attn_kernel(float* __restrict__ out)
{
    extern __shared__ char sm[];
    float* RS = (float*)(sm + OFF_RS);
    uint32_t* QHI = (uint32_t*)(sm + OFF_QHI);
    uint32_t* QLO = (uint32_t*)(sm + OFF_QLO);
    uint32_t* KHI = (uint32_t*)(sm + OFF_KHI);
    uint32_t* KLO = (uint32_t*)(sm + OFF_KLO);
    uint32_t* VHI = (uint32_t*)(sm + OFF_VHI);
    uint32_t* P   = (uint32_t*)(sm + OFF_P);

    const int bx = blockIdx.x;
    const int h  = bx & 7;
    const int qb = (bx >> 3) & 31;
    const int kb = bx >> 8;
    const int tid = threadIdx.x;
    const int warp = tid >> 5, lane = tid & 31;
    const int g = lane >> 2, t = lane & 3;

    // ---- staging: pure uint4 copies from pre-built gmem images
    {
        const uint4* sqh = (const uint4*)(g_Qhi + (size_t)(qb * 8 + h) * 4096);
        const uint4* sql = (const uint4*)(g_Qlo + (size_t)(qb * 8 + h) * 4096);
        uint4* dqh = (uint4*)QHI; uint4* dql = (uint4*)QLO;
        for (int i = tid; i < 1024; i += 256) {       // Q: 128 rows x 8 uint4
            const int r = i >> 3, c = i & 7;
            const int s = r * 8 + c, d = r * 9 + c;
            dqh[d] = sqh[s]; dql[d] = sql[s];
        }
        const uint4* skh = (const uint4*)(g_Khi + (size_t)(kb * 8 + h) * 4096);
        const uint4* skl = (const uint4*)(g_Klo + (size_t)(kb * 8 + h) * 4096);
        uint4* dkh = (uint4*)KHI; uint4* dkl = (uint4*)KLO;
        for (int i = tid; i < 896; i += 256) {        // K: 112 rows x 8 uint4
            const int r = i >> 3, c = i & 7;
            const int s = r * 8 + c, d = r * 9 + c;
            dkh[d] = skh[s]; dkl[d] = skl[s];
        }
        const uint4* svh = (const uint4*)(g_Vhi + (size_t)(kb * 8 + h) * 3840);
        uint4* dvh = (uint4*)VHI;
        for (int i = tid; i < 960; i += 256) dvh[i] = svh[i];
    }
    __syncthreads();

    const int wm = warp & 3, wn = warp >> 2;
    const int r0 = wm * 32;
    const int c0 = wn * 56;

    // ---- S phase: warp computes rows [r0,r0+32) x cols [c0,c0+56)
    // wn=1 skips j=6 (cols 104..111 entirely masked).
    float acc[2][7][4] = {};
    #pragma unroll
    for (int ks = 0; ks < 4; ks++) {
        uint32_t ah[2][4], al[2][4];
        #pragma unroll
        for (int i = 0; i < 2; i++) {
            const int rb = (r0 + 16 * i + g) * 36 + ks * 8 + t;
            ah[i][0] = QHI[rb];        al[i][0] = QLO[rb];
            ah[i][1] = QHI[rb + 288];  al[i][1] = QLO[rb + 288];
            ah[i][2] = QHI[rb + 4];    al[i][2] = QLO[rb + 4];
            ah[i][3] = QHI[rb + 292];  al[i][3] = QLO[rb + 292];
        }
        #pragma unroll
        for (int j = 0; j < 7; j++) {
            if (wn == 0 || j < 6) {
                const int nb = (c0 + 8 * j + g) * 36 + ks * 8 + t;
                const uint32_t bh0 = KHI[nb], bh1 = KHI[nb + 4];
                const uint32_t bl0 = KLO[nb], bl1 = KLO[nb + 4];
                #pragma unroll
                for (int i = 0; i < 2; i++) {
                    mma_f16(acc[i][j], ah[i][0], ah[i][1], ah[i][2], ah[i][3], bh0, bh1);
                    mma_f16(acc[i][j], ah[i][0], ah[i][1], ah[i][2], ah[i][3], bl0, bl1);
                    mma_f16(acc[i][j], al[i][0], al[i][1], al[i][2], al[i][3], bh0, bh1);
                }
            }
        }
    }
    __syncthreads();   // all Q reads done before P overlays Q smem

    // ---- epilogue: e = exp(20*relu(s) - ln8192), mask, pack fp16, rowsums
    {
        #pragma unroll
        for (int i = 0; i < 2; i++) {
            float rsg = 0.0f, rsg8 = 0.0f;
            #pragma unroll
            for (int j = 0; j < 7; j++) {
                const int col = c0 + 8 * j + 2 * t;
                const bool dead = (wn == 1 && j == 6);
                float e0 = 0.f, e1 = 0.f, e2 = 0.f, e3 = 0.f;
                if (!dead) {
                    e0 = __expf(fmaf(TEMP, fmaxf(acc[i][j][0], 0.f), -LN8192));
                    e1 = __expf(fmaf(TEMP, fmaxf(acc[i][j][1], 0.f), -LN8192));
                    e2 = __expf(fmaf(TEMP, fmaxf(acc[i][j][2], 0.f), -LN8192));
                    e3 = __expf(fmaf(TEMP, fmaxf(acc[i][j][3], 0.f), -LN8192));
                    if (col     >= LEN) { e0 = 0.f; e2 = 0.f; }
                    if (col + 1 >= LEN) { e1 = 0.f; e3 = 0.f; }
                }
                __half2 h01 = __floats2half2_rn(e0, e1);
                __half2 h23 = __floats2half2_rn(e2, e3);
                float2 f01 = __half22float2(h01);
                float2 f23 = __half22float2(h23);
                rsg  += f01.x + f01.y;
                rsg8 += f23.x + f23.y;
                const int w0 = (r0 + 16 * i + g) * 60 + (c0 >> 1) + j * 4 + t;
                P[w0]       = *(uint32_t*)&h01;
                P[w0 + 480] = *(uint32_t*)&h23;
            }
            rsg  += __shfl_xor_sync(0xffffffffu, rsg, 1);
            rsg  += __shfl_xor_sync(0xffffffffu, rsg, 2);
            rsg8 += __shfl_xor_sync(0xffffffffu, rsg8, 1);
            rsg8 += __shfl_xor_sync(0xffffffffu, rsg8, 2);
            if (t == 0) {
                RS[(r0 + 16 * i + g) * 2 + wn]     = rsg;
                RS[(r0 + 16 * i + g + 8) * 2 + wn] = rsg8;
            }
        }
    }
    __syncthreads();

    // ---- O phase: warp rows [r0,r0+32) x dv cols [wn*32,+32), K=112, 1-term
    float o[2][4][4] = {};
    #pragma unroll
    for (int ks = 0; ks < 7; ks++) {
        uint32_t a[2][4];
        #pragma unroll
        for (int i = 0; i < 2; i++) {
            const int rb = (r0 + 16 * i + g) * 60 + ks * 8 + t;
            a[i][0] = P[rb];        a[i][1] = P[rb + 480];
            a[i][2] = P[rb + 4];    a[i][3] = P[rb + 484];
        }
        #pragma unroll
        for (int j = 0; j < 4; j++) {
            const int nb = (wn * 32 + 8 * j + g) * 60 + ks * 8 + t;
            const uint32_t bh0 = VHI[nb], bh1 = VHI[nb + 4];
            #pragma unroll
            for (int i = 0; i < 2; i++) {
                mma_f16(o[i][j], a[i][0], a[i][1], a[i][2], a[i][3], bh0, bh1);
            }
        }
    }

    // ---- output: divide by rowsum, write [kb][qb][l][h*64+d]
    const size_t ob = (size_t)(kb * 32 + qb) * LEN * DMODEL + h * 64;
    #pragma unroll
    for (int i = 0; i < 2; i++) {
        const int r = r0 + 16 * i + g;
        float inv0 = 0.f, inv1 = 0.f;
        if (r < LEN)     inv0 = 1.0f / (RS[r * 2] + RS[r * 2 + 1]);
        if (r + 8 < LEN) inv1 = 1.0f / (RS[(r + 8) * 2] + RS[(r + 8) * 2 + 1]);
        #pragma unroll
        for (int j = 0; j < 4; j++) {
            const int cc = wn * 32 + 8 * j + 2 * t;
            if (r < LEN) {
                *(float2*)(out + ob + (size_t)r * DMODEL + cc) =
                    make_float2(o[i][j][0] * inv0, o[i][j][1] * inv0);
            }
            if (r + 8 < LEN) {
                *(float2*)(out + ob + (size_t)(r + 8) * DMODEL + cc) =
                    make_float2(o[i][j][2] * inv1, o[i][j][3] * inv1);
            }
        }
    }
}

// ---------------------------------------------------------------------------
extern "C" void kernel_launch(void* const* d_in, const int* in_sizes, int n_in,
                              void* d_out, int out_size)
{
    const float* q    = (const float*)d_in[0];
    const float* k    = (const float*)d_in[1];
    const float* v    = (const float*)d_in[2];
    const float* w_qs = (const float*)d_in[3];
    const float* w_ks = (const float*)d_in[4];
    float* out = (float*)d_out;

    cudaFuncSetAttribute(proj_kernel,
                         cudaFuncAttributeMaxDynamicSharedMemorySize, PJ_SMEM);
    cudaFuncSetAttribute(attn_kernel,
                         cudaFuncAttributeMaxDynamicSharedMemorySize, ATTN_SMEM);

    proj_kernel<<<dim3(8, 32, 2), 256, PJ_SMEM>>>(q, k, w_qs, w_ks);
    vimg_kernel<<<256, 256>>>(v);
    attn_kernel<<<8192, 256, ATTN_SMEM>>>(out);
}